// round 16
// baseline (speedup 1.0000x reference)
#include <cuda_runtime.h>

#define BATCH 8
#define N_SEQ 1024
#define CDIM  256
#define RREL  16

// Padded smem strides (R9: 2-way STS conflicts instead of 4-way)
#define SA 132
#define SB 68
#define SSC 68   // scores row stride (floats): 16B-aligned, 2-way conflicts max

// Scratch (device globals — no allocation allowed)
__device__ __align__(16) float g_A[BATCH * N_SEQ * CDIM];  // Q@Wq^T + bq  (8 MB)
__device__ __align__(16) float g_B[BATCH * N_SEQ * CDIM];  // K@Wk^T + bk  (8 MB)
__device__ __align__(16) float g_Rt[RREL * N_SEQ * N_SEQ]; // R_map transposed [r][i][j] (64 MB)

// ---------------------------------------------------------------------------
// mega (identical to R14 best): one launch for the whole pre-pass.
//   blocks [0,512):    projection GEMMs (p=0: g_A = Q@Wq^T+bq ; p=1: g_B = K@Wk^T+bk)
//   blocks [512,4608): Rt transpose (R_map[i][j][r] -> g_Rt[r][i][j])
// ---------------------------------------------------------------------------
__global__ __launch_bounds__(256, 2) void mega(const float* __restrict__ Q,
                                               const float* __restrict__ K,
                                               const float* __restrict__ Wq,
                                               const float* __restrict__ bq,
                                               const float* __restrict__ Wk,
                                               const float* __restrict__ bk,
                                               const float* __restrict__ Rmap) {
    __shared__ __align__(16) float smem[6400];   // union buffer (25.6 KB)
    int tid = threadIdx.x;
    int bx = blockIdx.x;

    if (bx < 512) {
        int p  = bx >> 8;
        int bb = bx & 255;
        int mt = bb & 3;
        int rt = bb >> 2;
        int tx = tid & 15;
        int ty = tid >> 4;
        int lrow = tid >> 2;
        int lk = (tid & 3) << 2;

        const float* src  = p ? K  : Q;
        const float* W    = p ? Wk : Wq;
        const float* bias = p ? bk : bq;
        float* dst        = p ? g_B : g_A;

        float (*As)[16][SA] = (float (*)[16][SA])smem;
        float (*Bs)[16][SB] = (float (*)[16][SB])(smem + 2 * 16 * SA);

        const float* Ap = src + (size_t)rt * 128 * CDIM;
        const float* Bp = W + (size_t)mt * 64 * CDIM;

        float4 ra0, ra1, rb0;
        auto ldg_stage = [&](int k0) {
            ra0 = *(const float4*)(Ap + (size_t)lrow * CDIM + k0 + lk);
            ra1 = *(const float4*)(Ap + (size_t)(64 + lrow) * CDIM + k0 + lk);
            rb0 = *(const float4*)(Bp + (size_t)lrow * CDIM + k0 + lk);
        };
        auto sts_stage = [&](int buf) {
            As[buf][lk + 0][lrow] = ra0.x; As[buf][lk + 1][lrow] = ra0.y;
            As[buf][lk + 2][lrow] = ra0.z; As[buf][lk + 3][lrow] = ra0.w;
            As[buf][lk + 0][64 + lrow] = ra1.x; As[buf][lk + 1][64 + lrow] = ra1.y;
            As[buf][lk + 2][64 + lrow] = ra1.z; As[buf][lk + 3][64 + lrow] = ra1.w;
            Bs[buf][lk + 0][lrow] = rb0.x; Bs[buf][lk + 1][lrow] = rb0.y;
            Bs[buf][lk + 2][lrow] = rb0.z; Bs[buf][lk + 3][lrow] = rb0.w;
        };

        float acc[8][4] = {};
        ldg_stage(0);
        sts_stage(0);
        __syncthreads();
        for (int s = 0; s < 16; s++) {
            int cur = s & 1;
            if (s < 15) ldg_stage((s + 1) * 16);
#pragma unroll
            for (int kk = 0; kk < 16; kk++) {
                float4 a0 = *(const float4*)&As[cur][kk][ty * 8];
                float4 a1 = *(const float4*)&As[cur][kk][ty * 8 + 4];
                float4 b0 = *(const float4*)&Bs[cur][kk][tx * 4];
                float av[8] = {a0.x, a0.y, a0.z, a0.w, a1.x, a1.y, a1.z, a1.w};
                float bv[4] = {b0.x, b0.y, b0.z, b0.w};
#pragma unroll
                for (int ii = 0; ii < 8; ii++)
#pragma unroll
                    for (int jj = 0; jj < 4; jj++)
                        acc[ii][jj] += av[ii] * bv[jj];
            }
            if (s < 15) {
                sts_stage(cur ^ 1);
                __syncthreads();
            }
        }

        int row = rt * 128 + ty * 8;
        int m = mt * 64 + tx * 4;
        float4 bv4 = *(const float4*)(bias + m);
#pragma unroll
        for (int ii = 0; ii < 8; ii++) {
            float4 o = {acc[ii][0] + bv4.x, acc[ii][1] + bv4.y,
                        acc[ii][2] + bv4.z, acc[ii][3] + bv4.w};
            *(float4*)&dst[(size_t)(row + ii) * CDIM + m] = o;
        }
        return;
    }

    // ================= Rt transpose branch =================
    {
        int tb = bx - 512;
        int i  = tb >> 2;
        int j0 = (tb & 3) << 8;
        float* s = smem;
        const float4* src = (const float4*)(Rmap + ((size_t)i * N_SEQ + j0) * RREL);
#pragma unroll
        for (int q = 0; q < 4; q++) {
            int idx = q * 256 + tid;
            float4 f = src[idx];
            int j = idx >> 2;
            int rq = (idx & 3) << 2;
            s[j * 17 + rq + 0] = f.x; s[j * 17 + rq + 1] = f.y;
            s[j * 17 + rq + 2] = f.z; s[j * 17 + rq + 3] = f.w;
        }
        __syncthreads();
        int jq = (tid & 63) << 2;
        int r0 = tid >> 6;
#pragma unroll
        for (int w = 0; w < 4; w++) {
            int r = r0 * 4 + w;
            float4 o;
            o.x = s[(jq + 0) * 17 + r];
            o.y = s[(jq + 1) * 17 + r];
            o.z = s[(jq + 2) * 17 + r];
            o.w = s[(jq + 3) * 17 + r];
            *(float4*)&g_Rt[((size_t)r * N_SEQ + i) * N_SEQ + j0 + jq] = o;
        }
    }
}

// ---------------------------------------------------------------------------
// main_fused v16: 128(i) x 64(j) tile, 8x4 micro, 256 threads, OCC-4.
// R16: scaled scores staged to smem between GEMM and epilogue (union with
// the dead As/Bs buffers) so the two phases' register pressures don't
// overlap -> fits the 64-reg occ-4 budget without spills (32 warps/SM).
//   scores = (g_A[b,i,:] . g_B[b,j,:]) / 16
//   out[b,r,i,j] = scores * Rt[r,i,j]
// ---------------------------------------------------------------------------
__global__ __launch_bounds__(256, 4) void main_fused(float* __restrict__ out) {
    // union buffer: GEMM tiles (6400 floats) then scores [128][SSC] (8704 floats)
    __shared__ __align__(16) float smem_u[128 * SSC];
    float (*As)[16][SA] = (float (*)[16][SA])smem_u;
    float (*Bs)[16][SB] = (float (*)[16][SB])(smem_u + 2 * 16 * SA);

    int b = blockIdx.x;
    int tile = blockIdx.y;        // 0..127
    int it = tile >> 4;           // 0..7   (128 i-rows each)
    int jt = tile & 15;           // 0..15  (64 j-cols each)
    int tid = threadIdx.x;
    int tx = tid & 15;            // j dir (4 each)
    int ty = tid >> 4;            // i dir (8 each)
    int lrow = tid >> 2;          // 0..63
    int lk = (tid & 3) << 2;      // 0,4,8,12

    const float* Ap = g_A + ((size_t)b * N_SEQ + it * 128) * CDIM;
    const float* Bp = g_B + ((size_t)b * N_SEQ + jt * 64) * CDIM;

    float4 ra0, ra1, rb0;

    auto ldg_stage = [&](int k0) {
        ra0 = *(const float4*)(Ap + (size_t)lrow * CDIM + k0 + lk);
        ra1 = *(const float4*)(Ap + (size_t)(64 + lrow) * CDIM + k0 + lk);
        rb0 = *(const float4*)(Bp + (size_t)lrow * CDIM + k0 + lk);
    };
    auto sts_stage = [&](int buf) {
        As[buf][lk + 0][lrow] = ra0.x; As[buf][lk + 1][lrow] = ra0.y;
        As[buf][lk + 2][lrow] = ra0.z; As[buf][lk + 3][lrow] = ra0.w;
        As[buf][lk + 0][64 + lrow] = ra1.x; As[buf][lk + 1][64 + lrow] = ra1.y;
        As[buf][lk + 2][64 + lrow] = ra1.z; As[buf][lk + 3][64 + lrow] = ra1.w;
        Bs[buf][lk + 0][lrow] = rb0.x; Bs[buf][lk + 1][lrow] = rb0.y;
        Bs[buf][lk + 2][lrow] = rb0.z; Bs[buf][lk + 3][lrow] = rb0.w;
    };

    float acc[8][4] = {};

    ldg_stage(0);
    sts_stage(0);
    __syncthreads();

    for (int s = 0; s < 16; s++) {
        int cur = s & 1;
        if (s < 15) ldg_stage((s + 1) * 16);
#pragma unroll
        for (int kk = 0; kk < 16; kk++) {
            float4 a0 = *(const float4*)&As[cur][kk][ty * 8];
            float4 a1 = *(const float4*)&As[cur][kk][ty * 8 + 4];
            float4 b0 = *(const float4*)&Bs[cur][kk][tx * 4];
            float av[8] = {a0.x, a0.y, a0.z, a0.w, a1.x, a1.y, a1.z, a1.w};
            float bv[4] = {b0.x, b0.y, b0.z, b0.w};
#pragma unroll
            for (int ii = 0; ii < 8; ii++)
#pragma unroll
                for (int jj = 0; jj < 4; jj++)
                    acc[ii][jj] += av[ii] * bv[jj];
        }
        if (s < 15) {
            sts_stage(cur ^ 1);    // ping-pong: single barrier per stage
            __syncthreads();
        }
    }

    // ---- stage scaled scores to smem (frees acc registers for epilogue) ----
    __syncthreads();   // all warps done reading As/Bs before overwrite
#pragma unroll
    for (int ii = 0; ii < 8; ii++) {
        int il = ty * 8 + ii;
        float4 sv = {acc[ii][0] * 0.0625f, acc[ii][1] * 0.0625f,
                     acc[ii][2] * 0.0625f, acc[ii][3] * 0.0625f};
        *(float4*)&smem_u[il * SSC + tx * 4] = sv;
    }
    // no barrier needed: each thread reads back only its own scores

    // ---- relation-mask multiply + streaming store (Rt: j-contiguous) ----
    int i0 = it * 128 + ty * 8;
    int j0 = jt * 64 + tx * 4;
    const size_t NN = (size_t)N_SEQ * N_SEQ;

#pragma unroll
    for (int ii = 0; ii < 8; ii++) {
        int il = ty * 8 + ii;
        float4 sv = *(const float4*)&smem_u[il * SSC + tx * 4];
        int i = i0 + ii;
        const float* rtp = g_Rt + (size_t)i * N_SEQ + j0;
        float* op = out + (size_t)(b * RREL) * NN + (size_t)i * N_SEQ + j0;
#pragma unroll
        for (int r = 0; r < RREL; r++) {
            float4 m0 = __ldg((const float4*)(rtp + (size_t)r * NN));
            float4 o0;
            o0.x = sv.x * m0.x;
            o0.y = sv.y * m0.y;
            o0.z = sv.z * m0.z;
            o0.w = sv.w * m0.w;
            __stcs((float4*)(op + (size_t)r * NN), o0);
        }
    }
}

// ---------------------------------------------------------------------------
extern "C" void kernel_launch(void* const* d_in, const int* in_sizes, int n_in,
                              void* d_out, int out_size) {
    const float* Q    = (const float*)d_in[0];
    const float* K    = (const float*)d_in[1];
    const float* Wq   = (const float*)d_in[2];
    const float* bq   = (const float*)d_in[3];
    const float* Wk   = (const float*)d_in[4];
    const float* bk   = (const float*)d_in[5];
    const float* Rmap = (const float*)d_in[6];
    float* out = (float*)d_out;

    mega<<<512 + 4096, 256>>>(Q, K, Wq, bq, Wk, bk, Rmap);
    main_fused<<<dim3(8, 128), 256>>>(out);
}

// round 17
// speedup vs baseline: 1.1945x; 1.1945x over previous
#include <cuda_runtime.h>
#include <cstdint>

#define BATCH 8
#define N_SEQ 1024
#define CDIM  256
#define RREL  16

// Padded smem strides (R9: 2-way STS conflicts instead of 4-way)
#define SA 132
#define SB 68

// Scratch (device globals — no allocation allowed)
__device__ __align__(16) float g_A[BATCH * N_SEQ * CDIM];  // Q@Wq^T + bq  (8 MB)
__device__ __align__(16) float g_B[BATCH * N_SEQ * CDIM];  // K@Wk^T + bk  (8 MB)
__device__ __align__(16) float g_Rt[RREL * N_SEQ * N_SEQ]; // R_map transposed [r][i][j] (64 MB)

// ---------------- packed fp32 helpers (fma.rn.f32x2: 2 IEEE FMAs / instr) ----
__device__ __forceinline__ void ffma2(unsigned long long& d,
                                      unsigned long long a,
                                      unsigned long long b) {
    asm volatile("fma.rn.f32x2 %0, %1, %2, %0;" : "+l"(d) : "l"(a), "l"(b));
}
__device__ __forceinline__ unsigned long long bcast2(float x) {
    unsigned long long r;
    asm("mov.b64 %0, {%1, %1};" : "=l"(r) : "f"(x));
    return r;
}
__device__ __forceinline__ float2 unpack2(unsigned long long v) {
    float2 r;
    asm("mov.b64 {%0, %1}, %2;" : "=f"(r.x), "=f"(r.y) : "l"(v));
    return r;
}

// ---------------------------------------------------------------------------
// mega: one launch for the whole pre-pass (R14 structure, FFMA2 inner loop).
//   blocks [0,512):    projection GEMMs (p=0: g_A = Q@Wq^T+bq ; p=1: g_B = K@Wk^T+bk)
//   blocks [512,4608): Rt transpose (R_map[i][j][r] -> g_Rt[r][i][j])
// ---------------------------------------------------------------------------
__global__ __launch_bounds__(256, 2) void mega(const float* __restrict__ Q,
                                               const float* __restrict__ K,
                                               const float* __restrict__ Wq,
                                               const float* __restrict__ bq,
                                               const float* __restrict__ Wk,
                                               const float* __restrict__ bk,
                                               const float* __restrict__ Rmap) {
    __shared__ __align__(16) float smem[6400];   // union buffer (25.6 KB)
    int tid = threadIdx.x;
    int bx = blockIdx.x;

    if (bx < 512) {
        int p  = bx >> 8;
        int bb = bx & 255;
        int mt = bb & 3;
        int rt = bb >> 2;
        int tx = tid & 15;
        int ty = tid >> 4;
        int lrow = tid >> 2;
        int lk = (tid & 3) << 2;

        const float* src  = p ? K  : Q;
        const float* W    = p ? Wk : Wq;
        const float* bias = p ? bk : bq;
        float* dst        = p ? g_B : g_A;

        float (*As)[16][SA] = (float (*)[16][SA])smem;
        float (*Bs)[16][SB] = (float (*)[16][SB])(smem + 2 * 16 * SA);

        const float* Ap = src + (size_t)rt * 128 * CDIM;
        const float* Bp = W + (size_t)mt * 64 * CDIM;

        float4 ra0, ra1, rb0;
        auto ldg_stage = [&](int k0) {
            ra0 = *(const float4*)(Ap + (size_t)lrow * CDIM + k0 + lk);
            ra1 = *(const float4*)(Ap + (size_t)(64 + lrow) * CDIM + k0 + lk);
            rb0 = *(const float4*)(Bp + (size_t)lrow * CDIM + k0 + lk);
        };
        auto sts_stage = [&](int buf) {
            As[buf][lk + 0][lrow] = ra0.x; As[buf][lk + 1][lrow] = ra0.y;
            As[buf][lk + 2][lrow] = ra0.z; As[buf][lk + 3][lrow] = ra0.w;
            As[buf][lk + 0][64 + lrow] = ra1.x; As[buf][lk + 1][64 + lrow] = ra1.y;
            As[buf][lk + 2][64 + lrow] = ra1.z; As[buf][lk + 3][64 + lrow] = ra1.w;
            Bs[buf][lk + 0][lrow] = rb0.x; Bs[buf][lk + 1][lrow] = rb0.y;
            Bs[buf][lk + 2][lrow] = rb0.z; Bs[buf][lk + 3][lrow] = rb0.w;
        };

        unsigned long long pacc[4][4] = {};   // (ii-pair, jj) packed fp32x2
        ldg_stage(0);
        sts_stage(0);
        __syncthreads();
        for (int s = 0; s < 16; s++) {
            int cur = s & 1;
            if (s < 15) ldg_stage((s + 1) * 16);
#pragma unroll
            for (int kk = 0; kk < 16; kk++) {
                const unsigned long long* ap =
                    (const unsigned long long*)&As[cur][kk][ty * 8];
                unsigned long long pa0 = ap[0], pa1 = ap[1],
                                   pa2 = ap[2], pa3 = ap[3];
                float4 b0 = *(const float4*)&Bs[cur][kk][tx * 4];
                unsigned long long pb0 = bcast2(b0.x), pb1 = bcast2(b0.y),
                                   pb2 = bcast2(b0.z), pb3 = bcast2(b0.w);
                ffma2(pacc[0][0], pa0, pb0); ffma2(pacc[0][1], pa0, pb1);
                ffma2(pacc[0][2], pa0, pb2); ffma2(pacc[0][3], pa0, pb3);
                ffma2(pacc[1][0], pa1, pb0); ffma2(pacc[1][1], pa1, pb1);
                ffma2(pacc[1][2], pa1, pb2); ffma2(pacc[1][3], pa1, pb3);
                ffma2(pacc[2][0], pa2, pb0); ffma2(pacc[2][1], pa2, pb1);
                ffma2(pacc[2][2], pa2, pb2); ffma2(pacc[2][3], pa2, pb3);
                ffma2(pacc[3][0], pa3, pb0); ffma2(pacc[3][1], pa3, pb1);
                ffma2(pacc[3][2], pa3, pb2); ffma2(pacc[3][3], pa3, pb3);
            }
            if (s < 15) {
                sts_stage(cur ^ 1);
                __syncthreads();
            }
        }

        float accf[8][4];
#pragma unroll
        for (int pp = 0; pp < 4; pp++)
#pragma unroll
            for (int jj = 0; jj < 4; jj++) {
                float2 t = unpack2(pacc[pp][jj]);
                accf[2 * pp + 0][jj] = t.x;
                accf[2 * pp + 1][jj] = t.y;
            }

        int row = rt * 128 + ty * 8;
        int m = mt * 64 + tx * 4;
        float4 bv4 = *(const float4*)(bias + m);
#pragma unroll
        for (int ii = 0; ii < 8; ii++) {
            float4 o = {accf[ii][0] + bv4.x, accf[ii][1] + bv4.y,
                        accf[ii][2] + bv4.z, accf[ii][3] + bv4.w};
            *(float4*)&dst[(size_t)(row + ii) * CDIM + m] = o;
        }
        return;
    }

    // ================= Rt transpose branch =================
    {
        int tb = bx - 512;
        int i  = tb >> 2;
        int j0 = (tb & 3) << 8;
        float* s = smem;
        const float4* src = (const float4*)(Rmap + ((size_t)i * N_SEQ + j0) * RREL);
#pragma unroll
        for (int q = 0; q < 4; q++) {
            int idx = q * 256 + tid;
            float4 f = src[idx];
            int j = idx >> 2;
            int rq = (idx & 3) << 2;
            s[j * 17 + rq + 0] = f.x; s[j * 17 + rq + 1] = f.y;
            s[j * 17 + rq + 2] = f.z; s[j * 17 + rq + 3] = f.w;
        }
        __syncthreads();
        int jq = (tid & 63) << 2;
        int r0 = tid >> 6;
#pragma unroll
        for (int w = 0; w < 4; w++) {
            int r = r0 * 4 + w;
            float4 o;
            o.x = s[(jq + 0) * 17 + r];
            o.y = s[(jq + 1) * 17 + r];
            o.z = s[(jq + 2) * 17 + r];
            o.w = s[(jq + 3) * 17 + r];
            *(float4*)&g_Rt[((size_t)r * N_SEQ + i) * N_SEQ + j0 + jq] = o;
        }
    }
}

// ---------------------------------------------------------------------------
// main_fused v17: R14 structure (128i x 64j tile, 256 thr, occ-3, register
// epilogue) with the GEMM inner loop in packed fp32 (fma.rn.f32x2):
// 16 FFMA2 per kk instead of 32 FFMA -> FFMA-issue floor halves.
//   scores = (g_A[b,i,:] . g_B[b,j,:]) / 16
//   out[b,r,i,j] = scores * Rt[r,i,j]
// ---------------------------------------------------------------------------
__global__ __launch_bounds__(256, 3) void main_fused(float* __restrict__ out) {
    int b = blockIdx.x;
    int tile = blockIdx.y;        // 0..127
    int it = tile >> 4;           // 0..7   (128 i-rows each)
    int jt = tile & 15;           // 0..15  (64 j-cols each)
    int tid = threadIdx.x;
    int tx = tid & 15;            // j dir (4 each)
    int ty = tid >> 4;            // i dir (8 each)
    int lrow = tid >> 2;          // 0..63
    int lk = (tid & 3) << 2;      // 0,4,8,12

    __shared__ __align__(16) float As[2][16][SA];
    __shared__ __align__(16) float Bs[2][16][SB];

    const float* Ap = g_A + ((size_t)b * N_SEQ + it * 128) * CDIM;
    const float* Bp = g_B + ((size_t)b * N_SEQ + jt * 64) * CDIM;

    float4 ra0, ra1, rb0;

    auto ldg_stage = [&](int k0) {
        ra0 = *(const float4*)(Ap + (size_t)lrow * CDIM + k0 + lk);
        ra1 = *(const float4*)(Ap + (size_t)(64 + lrow) * CDIM + k0 + lk);
        rb0 = *(const float4*)(Bp + (size_t)lrow * CDIM + k0 + lk);
    };
    auto sts_stage = [&](int buf) {
        As[buf][lk + 0][lrow] = ra0.x; As[buf][lk + 1][lrow] = ra0.y;
        As[buf][lk + 2][lrow] = ra0.z; As[buf][lk + 3][lrow] = ra0.w;
        As[buf][lk + 0][64 + lrow] = ra1.x; As[buf][lk + 1][64 + lrow] = ra1.y;
        As[buf][lk + 2][64 + lrow] = ra1.z; As[buf][lk + 3][64 + lrow] = ra1.w;
        Bs[buf][lk + 0][lrow] = rb0.x; Bs[buf][lk + 1][lrow] = rb0.y;
        Bs[buf][lk + 2][lrow] = rb0.z; Bs[buf][lk + 3][lrow] = rb0.w;
    };

    unsigned long long pacc[4][4] = {};   // (ii-pair, jj) packed fp32x2

    ldg_stage(0);
    sts_stage(0);
    __syncthreads();

    for (int s = 0; s < 16; s++) {
        int cur = s & 1;
        if (s < 15) ldg_stage((s + 1) * 16);
#pragma unroll
        for (int kk = 0; kk < 16; kk++) {
            const unsigned long long* ap =
                (const unsigned long long*)&As[cur][kk][ty * 8];
            unsigned long long pa0 = ap[0], pa1 = ap[1],
                               pa2 = ap[2], pa3 = ap[3];
            float4 b0 = *(const float4*)&Bs[cur][kk][tx * 4];
            unsigned long long pb0 = bcast2(b0.x), pb1 = bcast2(b0.y),
                               pb2 = bcast2(b0.z), pb3 = bcast2(b0.w);
            ffma2(pacc[0][0], pa0, pb0); ffma2(pacc[0][1], pa0, pb1);
            ffma2(pacc[0][2], pa0, pb2); ffma2(pacc[0][3], pa0, pb3);
            ffma2(pacc[1][0], pa1, pb0); ffma2(pacc[1][1], pa1, pb1);
            ffma2(pacc[1][2], pa1, pb2); ffma2(pacc[1][3], pa1, pb3);
            ffma2(pacc[2][0], pa2, pb0); ffma2(pacc[2][1], pa2, pb1);
            ffma2(pacc[2][2], pa2, pb2); ffma2(pacc[2][3], pa2, pb3);
            ffma2(pacc[3][0], pa3, pb0); ffma2(pacc[3][1], pa3, pb1);
            ffma2(pacc[3][2], pa3, pb2); ffma2(pacc[3][3], pa3, pb3);
        }
        if (s < 15) {
            sts_stage(cur ^ 1);    // ping-pong: single barrier per stage
            __syncthreads();
        }
    }

    // ---- unpack + scale (biases already folded into g_A/g_B) ----
    float accf[8][4];
#pragma unroll
    for (int pp = 0; pp < 4; pp++)
#pragma unroll
        for (int jj = 0; jj < 4; jj++) {
            float2 t = unpack2(pacc[pp][jj]);
            accf[2 * pp + 0][jj] = t.x * 0.0625f;
            accf[2 * pp + 1][jj] = t.y * 0.0625f;
        }

    // ---- relation-mask multiply + streaming store (Rt: j-contiguous) ----
    int i0 = it * 128 + ty * 8;
    int j0 = jt * 64 + tx * 4;
    const size_t NN = (size_t)N_SEQ * N_SEQ;

#pragma unroll
    for (int ii = 0; ii < 8; ii++) {
        int i = i0 + ii;
        const float* rtp = g_Rt + (size_t)i * N_SEQ + j0;
        float* op = out + (size_t)(b * RREL) * NN + (size_t)i * N_SEQ + j0;
#pragma unroll
        for (int r = 0; r < RREL; r++) {
            float4 m0 = __ldg((const float4*)(rtp + (size_t)r * NN));
            float4 o0;
            o0.x = accf[ii][0] * m0.x;
            o0.y = accf[ii][1] * m0.y;
            o0.z = accf[ii][2] * m0.z;
            o0.w = accf[ii][3] * m0.w;
            __stcs((float4*)(op + (size_t)r * NN), o0);
        }
    }
}

// ---------------------------------------------------------------------------
extern "C" void kernel_launch(void* const* d_in, const int* in_sizes, int n_in,
                              void* d_out, int out_size) {
    const float* Q    = (const float*)d_in[0];
    const float* K    = (const float*)d_in[1];
    const float* Wq   = (const float*)d_in[2];
    const float* bq   = (const float*)d_in[3];
    const float* Wk   = (const float*)d_in[4];
    const float* bk   = (const float*)d_in[5];
    const float* Rmap = (const float*)d_in[6];
    float* out = (float*)d_out;

    mega<<<512 + 4096, 256>>>(Q, K, Wq, bq, Wk, bk, Rmap);
    main_fused<<<dim3(8, 128), 256>>>(out);
}